// round 4
// baseline (speedup 1.0000x reference)
#include <cuda_runtime.h>
#include <cuda_bf16.h>
#include <cstdint>
#include <math_constants.h>

// Problem constants (B=64, T=256, C=1024, H=16, hd=64)
#define BB 64
#define TT 256
#define CC 1024
#define HH 16
#define HD 64
#define MM (BB*TT)   // 16384 rows

// ---------------- static device scratch (no allocation allowed) ----------------
__device__ __nv_bfloat16 g_xq[MM*CC];        // quantized x (int values as bf16)
__device__ float         g_xs[MM];           // per-row 1/s  (= clip(max,eps)/127)
__device__ __nv_bfloat16 g_yq[MM*CC];        // quantized attention output
__device__ float         g_ys[MM];
__device__ __nv_bfloat16 g_wq[4][CC*CC];     // ternary weights as bf16
__device__ double        g_wpart[4][32];     // partial |W| sums
__device__ float         g_ws_s[4];          // s  = 1/clip(mean,eps)
__device__ float         g_ws_inv[4];        // 1/s = clip(mean,eps)
__device__ float         g_q[MM*CC];         // [B,H,T,hd]
__device__ float         g_k[MM*CC];
__device__ float         g_v[MM*CC];
__device__ float         g_y[MM*CC];         // attention out, [B,T,C]

// ---------------- weight abs-sum (deterministic, fp64) ----------------
__global__ __launch_bounds__(256) void wsum_kernel(const float* __restrict__ w0,
                                                   const float* __restrict__ w1,
                                                   const float* __restrict__ w2,
                                                   const float* __restrict__ w3)
{
    const float* w = (blockIdx.y == 0) ? w0 : (blockIdx.y == 1) ? w1
                   : (blockIdx.y == 2) ? w2 : w3;
    int base = blockIdx.x * 32768;                 // 1,048,576 / 32 blocks
    const float4* w4 = (const float4*)(w + base);  // 8192 float4 per block
    double s = 0.0;
    for (int i = threadIdx.x; i < 8192; i += 256) {
        float4 v = w4[i];
        s += (double)(fabsf(v.x) + fabsf(v.y) + fabsf(v.z) + fabsf(v.w));
    }
    __shared__ double ds[256];
    ds[threadIdx.x] = s;
    __syncthreads();
    for (int st = 128; st; st >>= 1) {
        if (threadIdx.x < st) ds[threadIdx.x] += ds[threadIdx.x + st];
        __syncthreads();
    }
    if (threadIdx.x == 0) g_wpart[blockIdx.y][blockIdx.x] = ds[0];
}

__global__ void wscale_kernel()
{
    int i = threadIdx.x;
    if (i < 4) {
        double s = 0.0;
        for (int j = 0; j < 32; j++) s += g_wpart[i][j];
        float mean = (float)(s / (double)(CC * CC));
        float mc = fmaxf(mean, 1e-5f);
        g_ws_s[i]   = 1.0f / mc;
        g_ws_inv[i] = mc;
    }
}

// ---------------- ternary weight quantization -> bf16 ----------------
__global__ __launch_bounds__(256) void wquant_kernel(const float* __restrict__ src, int idx)
{
    float s = g_ws_s[idx];
    int gid = blockIdx.x * 256 + threadIdx.x;        // 1024 blocks -> 262144 float4
    float4 v = ((const float4*)src)[gid];
    float a = fminf(fmaxf(rintf(v.x * s), -1.f), 1.f);
    float b = fminf(fmaxf(rintf(v.y * s), -1.f), 1.f);
    float c = fminf(fmaxf(rintf(v.z * s), -1.f), 1.f);
    float d = fminf(fmaxf(rintf(v.w * s), -1.f), 1.f);
    __nv_bfloat162 p0 = __floats2bfloat162_rn(a, b);
    __nv_bfloat162 p1 = __floats2bfloat162_rn(c, d);
    __nv_bfloat162* out = (__nv_bfloat162*)g_wq[idx];
    out[gid * 2 + 0] = p0;
    out[gid * 2 + 1] = p1;
}

// ---------------- per-token int8 activation quantization -> bf16 ----------------
__global__ __launch_bounds__(256) void actquant_kernel(const float* __restrict__ xin, int sel)
{
    const float* src      = sel ? (const float*)g_y : xin;
    __nv_bfloat16* outq   = sel ? g_yq : g_xq;
    float* sinv           = sel ? g_ys : g_xs;

    int row = blockIdx.x;
    int tid = threadIdx.x;
    const float4* r4 = (const float4*)(src + (size_t)row * CC);
    float4 v = r4[tid];
    float mx = fmaxf(fmaxf(fabsf(v.x), fabsf(v.y)), fmaxf(fabsf(v.z), fabsf(v.w)));
    for (int o = 16; o; o >>= 1) mx = fmaxf(mx, __shfl_xor_sync(0xffffffffu, mx, o));
    __shared__ float wmax[8];
    if ((tid & 31) == 0) wmax[tid >> 5] = mx;
    __syncthreads();
    float am = wmax[0];
    #pragma unroll
    for (int i = 1; i < 8; i++) am = fmaxf(am, wmax[i]);
    float mc = fmaxf(am, 1e-5f);
    float s = 127.0f / mc;

    float a = fminf(fmaxf(rintf(v.x * s), -128.f), 127.f);
    float b = fminf(fmaxf(rintf(v.y * s), -128.f), 127.f);
    float c = fminf(fmaxf(rintf(v.z * s), -128.f), 127.f);
    float d = fminf(fmaxf(rintf(v.w * s), -128.f), 127.f);
    __nv_bfloat162* o2 = (__nv_bfloat162*)(outq + (size_t)row * CC);
    o2[tid * 2 + 0] = __floats2bfloat162_rn(a, b);
    o2[tid * 2 + 1] = __floats2bfloat162_rn(c, d);
    if (tid == 0) sinv[row] = mc / 127.0f;
}

// ---------------- bf16 MMA GEMM:  OUT[m,n] = (A[m,:] . W[n,:]) * sA[m] * sW ----------------
__device__ __forceinline__ void mma16816(float* c, const uint32_t* a, uint32_t b0, uint32_t b1)
{
    asm volatile(
        "mma.sync.aligned.m16n8k16.row.col.f32.bf16.bf16.f32 "
        "{%0,%1,%2,%3}, {%4,%5,%6,%7}, {%8,%9}, {%0,%1,%2,%3};\n"
        : "+f"(c[0]), "+f"(c[1]), "+f"(c[2]), "+f"(c[3])
        : "r"(a[0]), "r"(a[1]), "r"(a[2]), "r"(a[3]), "r"(b0), "r"(b1));
}

#define BM 128
#define BN 128
#define BK 32
#define LDS_STRIDE 40   // BK + 8 pad -> conflict-free fragment loads

__global__ __launch_bounds__(256) void gemm_kernel(int a_sel, int w_idx, int mode,
                                                   float* __restrict__ dst,
                                                   const float* __restrict__ bias)
{
    __shared__ __nv_bfloat16 As[BM * LDS_STRIDE];
    __shared__ __nv_bfloat16 Bs[BN * LDS_STRIDE];

    const __nv_bfloat16* __restrict__ A  = a_sel ? g_yq : g_xq;
    const float* __restrict__ sA         = a_sel ? g_ys : g_xs;
    const __nv_bfloat16* __restrict__ W  = g_wq[w_idx];

    int m0 = blockIdx.x * BM;
    int n0 = blockIdx.y * BN;
    int tid = threadIdx.x;
    int warp = tid >> 5, lane = tid & 31;
    int wm = warp >> 1, wn = warp & 1;     // 4x2 warp grid, warp tile 32x64
    int g = lane >> 2, tg = lane & 3;

    float acc[2][8][4];
    #pragma unroll
    for (int i = 0; i < 2; i++)
        #pragma unroll
        for (int j = 0; j < 8; j++)
            #pragma unroll
            for (int r = 0; r < 4; r++) acc[i][j][r] = 0.f;

    for (int k0 = 0; k0 < CC; k0 += BK) {
        #pragma unroll
        for (int i = 0; i < 4; i++) {
            int idx = tid + i * 256;           // 0..1023
            int r = idx >> 3, c4 = (idx & 7) * 4;
            *(uint2*)&As[r * LDS_STRIDE + c4] =
                *(const uint2*)&A[(m0 + r) * CC + k0 + c4];
            *(uint2*)&Bs[r * LDS_STRIDE + c4] =
                *(const uint2*)&W[(n0 + r) * CC + k0 + c4];
        }
        __syncthreads();
        #pragma unroll
        for (int ks = 0; ks < BK; ks += 16) {
            uint32_t a[2][4];
            #pragma unroll
            for (int i = 0; i < 2; i++) {
                int row = wm * 32 + i * 16;
                a[i][0] = *(uint32_t*)&As[(row +     g) * LDS_STRIDE + ks + tg * 2];
                a[i][1] = *(uint32_t*)&As[(row + 8 + g) * LDS_STRIDE + ks + tg * 2];
                a[i][2] = *(uint32_t*)&As[(row +     g) * LDS_STRIDE + ks + tg * 2 + 8];
                a[i][3] = *(uint32_t*)&As[(row + 8 + g) * LDS_STRIDE + ks + tg * 2 + 8];
            }
            #pragma unroll
            for (int j = 0; j < 8; j++) {
                int n = wn * 64 + j * 8 + g;
                uint32_t b0 = *(uint32_t*)&Bs[n * LDS_STRIDE + ks + tg * 2];
                uint32_t b1 = *(uint32_t*)&Bs[n * LDS_STRIDE + ks + tg * 2 + 8];
                mma16816(acc[0][j], a[0], b0, b1);
                mma16816(acc[1][j], a[1], b0, b1);
            }
        }
        __syncthreads();
    }

    // epilogue: scale + write
    float sw = g_ws_inv[w_idx];
    float* sc = (mode == 0) ? g_q : (mode == 1) ? g_k : g_v;   // scatter targets
    #pragma unroll
    for (int i = 0; i < 2; i++) {
        int r0 = m0 + wm * 32 + i * 16 + g;
        float s0 = sA[r0] * sw;
        float s1 = sA[r0 + 8] * sw;
        #pragma unroll
        for (int j = 0; j < 8; j++) {
            int c = n0 + wn * 64 + j * 8 + tg * 2;
            float v00 = acc[i][j][0] * s0, v01 = acc[i][j][1] * s0;
            float v10 = acc[i][j][2] * s1, v11 = acc[i][j][3] * s1;
            if (mode == 3) {
                float b0 = bias[c], b1 = bias[c + 1];
                float2* p0 = (float2*)&dst[r0 * CC + c];
                float2* p1 = (float2*)&dst[(r0 + 8) * CC + c];
                *p0 = make_float2(v00 + b0, v01 + b1);
                *p1 = make_float2(v10 + b0, v11 + b1);
            } else {
                int h = c >> 6, d = c & 63;
                {
                    int m = r0, t = m & (TT - 1), b = m >> 8;
                    float2* p = (float2*)&sc[(((b * HH + h) * TT + t) * HD) + d];
                    *p = make_float2(v00, v01);
                }
                {
                    int m = r0 + 8, t = m & (TT - 1), b = m >> 8;
                    float2* p = (float2*)&sc[(((b * HH + h) * TT + t) * HD) + d];
                    *p = make_float2(v10, v11);
                }
            }
        }
    }
}

// ---------------- fused causal attention, one (b,h) per CTA ----------------
// smem: K tile [256][64] + V tile [256][64] fp32 = 131072 B (dynamic)
__global__ __launch_bounds__(256) void attn_kernel()
{
    extern __shared__ float sm[];
    float* Ks = sm;
    float* Vs = sm + TT * HD;

    int bh = blockIdx.x;               // 0..1023
    size_t base = (size_t)bh * (TT * HD);
    int tid = threadIdx.x;             // = query row t

    // fill K/V tiles (coalesced float4)
    const float4* k4 = (const float4*)(g_k + base);
    const float4* v4 = (const float4*)(g_v + base);
    float4* Ks4 = (float4*)Ks;
    float4* Vs4 = (float4*)Vs;
    #pragma unroll
    for (int i = tid; i < TT * HD / 4; i += 256) {
        Ks4[i] = k4[i];
        Vs4[i] = v4[i];
    }

    // q row in registers
    float4 q[16];
    const float4* qg = (const float4*)(g_q + base + (size_t)tid * HD);
    #pragma unroll
    for (int i = 0; i < 16; i++) q[i] = qg[i];
    __syncthreads();

    float m = -CUDART_INF_F, l = 0.f;
    float4 o[16];
    #pragma unroll
    for (int i = 0; i < 16; i++) o[i] = make_float4(0.f, 0.f, 0.f, 0.f);

    for (int j = 0; j <= tid; j++) {
        const float4* kj = (const float4*)(Ks + j * HD);   // warp-broadcast
        float s0 = 0.f, s1 = 0.f, s2 = 0.f, s3 = 0.f;
        #pragma unroll
        for (int i = 0; i < 16; i += 4) {
            float4 a = kj[i], b = kj[i + 1], c = kj[i + 2], d = kj[i + 3];
            s0 += q[i].x * a.x + q[i].y * a.y + q[i].z * a.z + q[i].w * a.w;
            s1 += q[i+1].x * b.x + q[i+1].y * b.y + q[i+1].z * b.z + q[i+1].w * b.w;
            s2 += q[i+2].x * c.x + q[i+2].y * c.y + q[i+2].z * c.z + q[i+2].w * c.w;
            s3 += q[i+3].x * d.x + q[i+3].y * d.y + q[i+3].z * d.z + q[i+3].w * d.w;
        }
        float s = ((s0 + s1) + (s2 + s3)) * 0.125f;   // 1/sqrt(64)

        float p;
        if (s <= m) {
            p = __expf(s - m);
        } else {
            float corr = __expf(m - s);               // exp(-inf)=0 on first iter
            l *= corr;
            #pragma unroll
            for (int i = 0; i < 16; i++) {
                o[i].x *= corr; o[i].y *= corr; o[i].z *= corr; o[i].w *= corr;
            }
            m = s;
            p = 1.f;
        }
        l += p;
        const float4* vj = (const float4*)(Vs + j * HD);  // warp-broadcast
        #pragma unroll
        for (int i = 0; i < 16; i++) {
            float4 vv = vj[i];
            o[i].x += p * vv.x; o[i].y += p * vv.y;
            o[i].z += p * vv.z; o[i].w += p * vv.w;
        }
    }

    float inv = 1.0f / l;
    int b = bh >> 4, h = bh & (HH - 1);
    float4* yout = (float4*)(g_y + ((size_t)(b * TT + tid)) * CC + h * HD);
    #pragma unroll
    for (int i = 0; i < 16; i++) {
        float4 t = o[i];
        t.x *= inv; t.y *= inv; t.z *= inv; t.w *= inv;
        yout[i] = t;
    }
}

// ---------------- launch ----------------
extern "C" void kernel_launch(void* const* d_in, const int* in_sizes, int n_in,
                              void* d_out, int out_size)
{
    const float* x  = (const float*)d_in[0];
    const float* Wq = (const float*)d_in[1];
    const float* Wk = (const float*)d_in[2];
    const float* Wv = (const float*)d_in[3];
    const float* Wp = (const float*)d_in[4];
    const float* bp = (const float*)d_in[5];
    float* out = (float*)d_out;

    // 1) weight scales (deterministic fp64 two-pass)
    wsum_kernel<<<dim3(32, 4), 256>>>(Wq, Wk, Wv, Wp);
    wscale_kernel<<<1, 32>>>();

    // 2) ternary-quantize weights to bf16
    wquant_kernel<<<1024, 256>>>(Wq, 0);
    wquant_kernel<<<1024, 256>>>(Wk, 1);
    wquant_kernel<<<1024, 256>>>(Wv, 2);
    wquant_kernel<<<1024, 256>>>(Wp, 3);

    // 3) per-token quantize x
    actquant_kernel<<<MM, 256>>>(x, 0);

    // 4) Q/K/V projections (exact integer MMA), scatter to [B,H,T,hd]
    dim3 ggrid(MM / BM, CC / BN);
    gemm_kernel<<<ggrid, 256>>>(0, 0, 0, nullptr, nullptr);
    gemm_kernel<<<ggrid, 256>>>(0, 1, 1, nullptr, nullptr);
    gemm_kernel<<<ggrid, 256>>>(0, 2, 2, nullptr, nullptr);

    // 5) fused causal attention
    cudaFuncSetAttribute(attn_kernel, cudaFuncAttributeMaxDynamicSharedMemorySize, 131072);
    attn_kernel<<<BB * HH, 256, 131072>>>();

    // 6) quantize attention output
    actquant_kernel<<<MM, 256>>>(nullptr, 1);

    // 7) output projection (+bias) straight into d_out
    gemm_kernel<<<ggrid, 256>>>(1, 3, 3, out, bp);
}

// round 5
// speedup vs baseline: 1.1819x; 1.1819x over previous
#include <cuda_runtime.h>
#include <cuda_bf16.h>
#include <cstdint>
#include <math_constants.h>

// Problem constants (B=64, T=256, C=1024, H=16, hd=64)
#define BB 64
#define TT 256
#define CC 1024
#define HH 16
#define HD 64
#define MM (BB*TT)   // 16384 rows

// ---------------- static device scratch (no allocation allowed) ----------------
__device__ __nv_bfloat16 g_xq[MM*CC];        // quantized x (int values as bf16)
__device__ float         g_xs[MM];           // per-row 1/s  (= clip(max,eps)/127)
__device__ __nv_bfloat16 g_yq[MM*CC];        // quantized attention output
__device__ float         g_ys[MM];
__device__ __nv_bfloat16 g_wq[4][CC*CC];     // ternary weights as bf16
__device__ double        g_wpart[4][32];     // partial |W| sums
__device__ float         g_ws_s[4];          // s  = 1/clip(mean,eps)
__device__ float         g_ws_inv[4];        // 1/s = clip(mean,eps)
__device__ float         g_q[MM*CC];         // [B,H,T,hd]
__device__ float         g_k[MM*CC];
__device__ float         g_v[MM*CC];
__device__ float         g_y[MM*CC];         // attention out, [B,T,C]

// ---------------- packed f32x2 helpers (sm_103a FFMA2) ----------------
#define FMA2(d, a, b) asm volatile("fma.rn.f32x2 %0, %1, %2, %0;" : "+l"(d) : "l"(a), "l"(b))
#define MUL2(d, a)    asm volatile("mul.rn.f32x2 %0, %0, %1;"     : "+l"(d) : "l"(a))
__device__ __forceinline__ unsigned long long pack2(float lo, float hi) {
    unsigned long long r;
    asm("mov.b64 %0, {%1, %2};" : "=l"(r) : "f"(lo), "f"(hi));
    return r;
}
__device__ __forceinline__ void unpack2(unsigned long long v, float& lo, float& hi) {
    asm("mov.b64 {%0, %1}, %2;" : "=f"(lo), "=f"(hi) : "l"(v));
}

// ---------------- cp.async helpers ----------------
__device__ __forceinline__ void cpasync16(void* smem_ptr, const void* gmem_ptr) {
    uint32_t s = (uint32_t)__cvta_generic_to_shared(smem_ptr);
    asm volatile("cp.async.cg.shared.global [%0], [%1], 16;\n" :: "r"(s), "l"(gmem_ptr));
}
#define CP_COMMIT() asm volatile("cp.async.commit_group;\n")
#define CP_WAIT(N)  asm volatile("cp.async.wait_group %0;\n" :: "n"(N))

// ---------------- weight abs-sum (deterministic, fp64) ----------------
__global__ __launch_bounds__(256) void wsum_kernel(const float* __restrict__ w0,
                                                   const float* __restrict__ w1,
                                                   const float* __restrict__ w2,
                                                   const float* __restrict__ w3)
{
    const float* w = (blockIdx.y == 0) ? w0 : (blockIdx.y == 1) ? w1
                   : (blockIdx.y == 2) ? w2 : w3;
    int base = blockIdx.x * 32768;
    const float4* w4 = (const float4*)(w + base);
    double s = 0.0;
    for (int i = threadIdx.x; i < 8192; i += 256) {
        float4 v = w4[i];
        s += (double)(fabsf(v.x) + fabsf(v.y) + fabsf(v.z) + fabsf(v.w));
    }
    __shared__ double ds[256];
    ds[threadIdx.x] = s;
    __syncthreads();
    for (int st = 128; st; st >>= 1) {
        if (threadIdx.x < st) ds[threadIdx.x] += ds[threadIdx.x + st];
        __syncthreads();
    }
    if (threadIdx.x == 0) g_wpart[blockIdx.y][blockIdx.x] = ds[0];
}

__global__ void wscale_kernel()
{
    int i = threadIdx.x;
    if (i < 4) {
        double s = 0.0;
        for (int j = 0; j < 32; j++) s += g_wpart[i][j];
        float mean = (float)(s / (double)(CC * CC));
        float mc = fmaxf(mean, 1e-5f);
        g_ws_s[i]   = 1.0f / mc;
        g_ws_inv[i] = mc;
    }
}

// ---------------- ternary weight quantization -> bf16 (all 4 weights, grid.y) ----------------
__global__ __launch_bounds__(256) void wquant_kernel(const float* __restrict__ w0,
                                                     const float* __restrict__ w1,
                                                     const float* __restrict__ w2,
                                                     const float* __restrict__ w3)
{
    int idx = blockIdx.y;
    const float* src = (idx == 0) ? w0 : (idx == 1) ? w1 : (idx == 2) ? w2 : w3;
    float s = g_ws_s[idx];
    int gid = blockIdx.x * 256 + threadIdx.x;        // 1024 blocks -> 262144 float4
    float4 v = ((const float4*)src)[gid];
    float a = fminf(fmaxf(rintf(v.x * s), -1.f), 1.f);
    float b = fminf(fmaxf(rintf(v.y * s), -1.f), 1.f);
    float c = fminf(fmaxf(rintf(v.z * s), -1.f), 1.f);
    float d = fminf(fmaxf(rintf(v.w * s), -1.f), 1.f);
    __nv_bfloat162* out = (__nv_bfloat162*)g_wq[idx];
    out[gid * 2 + 0] = __floats2bfloat162_rn(a, b);
    out[gid * 2 + 1] = __floats2bfloat162_rn(c, d);
}

// ---------------- per-token int8 activation quantization -> bf16 ----------------
__global__ __launch_bounds__(256) void actquant_kernel(const float* __restrict__ xin, int sel)
{
    const float* src      = sel ? (const float*)g_y : xin;
    __nv_bfloat16* outq   = sel ? g_yq : g_xq;
    float* sinv           = sel ? g_ys : g_xs;

    int row = blockIdx.x;
    int tid = threadIdx.x;
    const float4* r4 = (const float4*)(src + (size_t)row * CC);
    float4 v = r4[tid];
    float mx = fmaxf(fmaxf(fabsf(v.x), fabsf(v.y)), fmaxf(fabsf(v.z), fabsf(v.w)));
    for (int o = 16; o; o >>= 1) mx = fmaxf(mx, __shfl_xor_sync(0xffffffffu, mx, o));
    __shared__ float wmax[8];
    if ((tid & 31) == 0) wmax[tid >> 5] = mx;
    __syncthreads();
    float am = wmax[0];
    #pragma unroll
    for (int i = 1; i < 8; i++) am = fmaxf(am, wmax[i]);
    float mc = fmaxf(am, 1e-5f);
    float s = 127.0f / mc;

    float a = fminf(fmaxf(rintf(v.x * s), -128.f), 127.f);
    float b = fminf(fmaxf(rintf(v.y * s), -128.f), 127.f);
    float c = fminf(fmaxf(rintf(v.z * s), -128.f), 127.f);
    float d = fminf(fmaxf(rintf(v.w * s), -128.f), 127.f);
    __nv_bfloat162* o2 = (__nv_bfloat162*)(outq + (size_t)row * CC);
    o2[tid * 2 + 0] = __floats2bfloat162_rn(a, b);
    o2[tid * 2 + 1] = __floats2bfloat162_rn(c, d);
    if (tid == 0) sinv[row] = mc / 127.0f;
}

// ---------------- bf16 MMA GEMM with cp.async double buffering ----------------
__device__ __forceinline__ void mma16816(float* c, const uint32_t* a, uint32_t b0, uint32_t b1)
{
    asm volatile(
        "mma.sync.aligned.m16n8k16.row.col.f32.bf16.bf16.f32 "
        "{%0,%1,%2,%3}, {%4,%5,%6,%7}, {%8,%9}, {%0,%1,%2,%3};\n"
        : "+f"(c[0]), "+f"(c[1]), "+f"(c[2]), "+f"(c[3])
        : "r"(a[0]), "r"(a[1]), "r"(a[2]), "r"(a[3]), "r"(b0), "r"(b1));
}

#define BM 128
#define BN 128
#define BK 64
#define AST 72   // smem stride in halves (64 + 8 pad): 144B rows, conflict-free, 16B-aligned
#define GEMM_SMEM (4 * BM * AST * 2)   // 2 stages x (A + B) = 73728 bytes

__global__ __launch_bounds__(256) void gemm_kernel(int qkv, int w_idx_p, int mode_p,
                                                   float* __restrict__ dst,
                                                   const float* __restrict__ bias)
{
    extern __shared__ __align__(16) __nv_bfloat16 smem[];
    __nv_bfloat16* As = smem;                 // [2][BM*AST]
    __nv_bfloat16* Bs = smem + 2 * BM * AST;  // [2][BN*AST]

    int w_idx = qkv ? (int)blockIdx.z : w_idx_p;
    int mode  = qkv ? (int)blockIdx.z : mode_p;

    const __nv_bfloat16* __restrict__ A  = qkv ? g_xq : g_yq;
    const float* __restrict__ sA         = qkv ? g_xs : g_ys;
    const __nv_bfloat16* __restrict__ W  = g_wq[w_idx];

    int m0 = blockIdx.x * BM;
    int n0 = blockIdx.y * BN;
    int tid = threadIdx.x;
    int warp = tid >> 5, lane = tid & 31;
    int wm = warp >> 1, wn = warp & 1;     // 4x2 warp grid, warp tile 32x64
    int g = lane >> 2, tg = lane & 3;

    float acc[2][8][4];
    #pragma unroll
    for (int i = 0; i < 2; i++)
        #pragma unroll
        for (int j = 0; j < 8; j++)
            #pragma unroll
            for (int r = 0; r < 4; r++) acc[i][j][r] = 0.f;

    // stage loader: 1024 16B chunks per matrix, 8 cp.async per thread
    auto load_stage = [&](int s, int kk) {
        #pragma unroll
        for (int i = 0; i < 4; i++) {
            int idx = tid + i * 256;             // 0..1023
            int r = idx >> 3, c = (idx & 7) * 8; // c: halves 0..56
            cpasync16(&As[s * BM * AST + r * AST + c],
                      &A[(size_t)(m0 + r) * CC + kk + c]);
            cpasync16(&Bs[s * BN * AST + r * AST + c],
                      &W[(size_t)(n0 + r) * CC + kk + c]);
        }
    };

    load_stage(0, 0);
    CP_COMMIT();

    const int NT = CC / BK;   // 16
    for (int t = 0; t < NT; t++) {
        if (t + 1 < NT) {
            load_stage((t + 1) & 1, (t + 1) * BK);
            CP_COMMIT();
            CP_WAIT(1);
        } else {
            CP_WAIT(0);
        }
        __syncthreads();

        const __nv_bfloat16* Ab = &As[(t & 1) * BM * AST];
        const __nv_bfloat16* Bb = &Bs[(t & 1) * BN * AST];
        #pragma unroll
        for (int ks = 0; ks < BK; ks += 16) {
            uint32_t a[2][4];
            #pragma unroll
            for (int i = 0; i < 2; i++) {
                int row = wm * 32 + i * 16;
                a[i][0] = *(const uint32_t*)&Ab[(row +     g) * AST + ks + tg * 2];
                a[i][1] = *(const uint32_t*)&Ab[(row + 8 + g) * AST + ks + tg * 2];
                a[i][2] = *(const uint32_t*)&Ab[(row +     g) * AST + ks + tg * 2 + 8];
                a[i][3] = *(const uint32_t*)&Ab[(row + 8 + g) * AST + ks + tg * 2 + 8];
            }
            #pragma unroll
            for (int j = 0; j < 8; j++) {
                int n = wn * 64 + j * 8 + g;
                uint32_t b0 = *(const uint32_t*)&Bb[n * AST + ks + tg * 2];
                uint32_t b1 = *(const uint32_t*)&Bb[n * AST + ks + tg * 2 + 8];
                mma16816(acc[0][j], a[0], b0, b1);
                mma16816(acc[1][j], a[1], b0, b1);
            }
        }
        __syncthreads();
    }

    // epilogue: scale + write
    float sw = g_ws_inv[w_idx];
    float* sc = (mode == 0) ? g_q : (mode == 1) ? g_k : g_v;   // scatter targets
    #pragma unroll
    for (int i = 0; i < 2; i++) {
        int r0 = m0 + wm * 32 + i * 16 + g;
        float s0 = sA[r0] * sw;
        float s1 = sA[r0 + 8] * sw;
        #pragma unroll
        for (int j = 0; j < 8; j++) {
            int c = n0 + wn * 64 + j * 8 + tg * 2;
            float v00 = acc[i][j][0] * s0, v01 = acc[i][j][1] * s0;
            float v10 = acc[i][j][2] * s1, v11 = acc[i][j][3] * s1;
            if (mode == 3) {
                float b0 = bias[c], b1 = bias[c + 1];
                float2* p0 = (float2*)&dst[(size_t)r0 * CC + c];
                float2* p1 = (float2*)&dst[(size_t)(r0 + 8) * CC + c];
                *p0 = make_float2(v00 + b0, v01 + b1);
                *p1 = make_float2(v10 + b0, v11 + b1);
            } else {
                int h = c >> 6, d = c & 63;
                {
                    int m = r0, t2 = m & (TT - 1), b = m >> 8;
                    float2* p = (float2*)&sc[(((b * HH + h) * TT + t2) * HD) + d];
                    *p = make_float2(v00, v01);
                }
                {
                    int m = r0 + 8, t2 = m & (TT - 1), b = m >> 8;
                    float2* p = (float2*)&sc[(((b * HH + h) * TT + t2) * HD) + d];
                    *p = make_float2(v10, v11);
                }
            }
        }
    }
}

// ---------------- fused causal attention, one (b,h) per CTA, packed f32x2 math ----------------
// smem: K tile [256][64] + V tile [256][64] fp32 = 131072 B (dynamic)
__global__ __launch_bounds__(256) void attn_kernel()
{
    extern __shared__ float sm[];
    float* Ks = sm;
    float* Vs = sm + TT * HD;

    int bh = blockIdx.x;               // 0..1023
    size_t base = (size_t)bh * (TT * HD);
    int tid = threadIdx.x;             // = query row t

    // fill K/V tiles (coalesced float4)
    const float4* k4 = (const float4*)(g_k + base);
    const float4* v4 = (const float4*)(g_v + base);
    float4* Ks4 = (float4*)Ks;
    float4* Vs4 = (float4*)Vs;
    #pragma unroll
    for (int i = tid; i < TT * HD / 4; i += 256) {
        Ks4[i] = k4[i];
        Vs4[i] = v4[i];
    }

    // q row in registers (as packed f32x2)
    unsigned long long q2[32];
    const ulonglong2* qg = (const ulonglong2*)(g_q + base + (size_t)tid * HD);
    #pragma unroll
    for (int i = 0; i < 16; i++) {
        ulonglong2 u = qg[i];
        q2[2 * i] = u.x; q2[2 * i + 1] = u.y;
    }
    __syncthreads();

    float m = -CUDART_INF_F, l = 0.f;
    unsigned long long o2[32];
    #pragma unroll
    for (int i = 0; i < 32; i++) o2[i] = 0ULL;

    for (int j = 0; j <= tid; j++) {
        const ulonglong2* kj = (const ulonglong2*)(Ks + j * HD);   // warp-broadcast
        unsigned long long acc[4] = {0ULL, 0ULL, 0ULL, 0ULL};
        #pragma unroll
        for (int c = 0; c < 16; c++) {
            ulonglong2 kv = kj[c];
            FMA2(acc[c & 3], q2[2 * c],     kv.x);
            FMA2(acc[c & 3], q2[2 * c + 1], kv.y);
        }
        float a0, a1, b0, b1, c0, c1, d0, d1;
        unpack2(acc[0], a0, a1); unpack2(acc[1], b0, b1);
        unpack2(acc[2], c0, c1); unpack2(acc[3], d0, d1);
        float s = (((a0 + a1) + (b0 + b1)) + ((c0 + c1) + (d0 + d1))) * 0.125f; // 1/sqrt(64)

        float p;
        if (s <= m) {
            p = __expf(s - m);
        } else {
            float corr = __expf(m - s);               // exp(-inf)=0 on first iter
            l *= corr;
            unsigned long long corr2 = pack2(corr, corr);
            #pragma unroll
            for (int i = 0; i < 32; i++) MUL2(o2[i], corr2);
            m = s;
            p = 1.f;
        }
        l += p;
        unsigned long long p2 = pack2(p, p);
        const ulonglong2* vj = (const ulonglong2*)(Vs + j * HD);  // warp-broadcast
        #pragma unroll
        for (int c = 0; c < 16; c++) {
            ulonglong2 vv = vj[c];
            FMA2(o2[2 * c],     p2, vv.x);
            FMA2(o2[2 * c + 1], p2, vv.y);
        }
    }

    float inv = 1.0f / l;
    unsigned long long inv2 = pack2(inv, inv);
    int b = bh >> 4, h = bh & (HH - 1);
    unsigned long long* yout =
        (unsigned long long*)(g_y + ((size_t)(b * TT + tid)) * CC + h * HD);
    #pragma unroll
    for (int c = 0; c < 32; c++) {
        MUL2(o2[c], inv2);
        yout[c] = o2[c];
    }
}

// ---------------- launch ----------------
extern "C" void kernel_launch(void* const* d_in, const int* in_sizes, int n_in,
                              void* d_out, int out_size)
{
    const float* x  = (const float*)d_in[0];
    const float* Wq = (const float*)d_in[1];
    const float* Wk = (const float*)d_in[2];
    const float* Wv = (const float*)d_in[3];
    const float* Wp = (const float*)d_in[4];
    const float* bp = (const float*)d_in[5];
    float* out = (float*)d_out;

    cudaFuncSetAttribute(gemm_kernel, cudaFuncAttributeMaxDynamicSharedMemorySize, GEMM_SMEM);
    cudaFuncSetAttribute(attn_kernel, cudaFuncAttributeMaxDynamicSharedMemorySize, 131072);

    // 1) weight scales (deterministic fp64 two-pass)
    wsum_kernel<<<dim3(32, 4), 256>>>(Wq, Wk, Wv, Wp);
    wscale_kernel<<<1, 32>>>();

    // 2) ternary-quantize all 4 weights to bf16 (one launch)
    wquant_kernel<<<dim3(1024, 4), 256>>>(Wq, Wk, Wv, Wp);

    // 3) per-token quantize x
    actquant_kernel<<<MM, 256>>>(x, 0);

    // 4) Q/K/V projections fused in one launch (exact integer MMA), scatter to [B,H,T,hd]
    gemm_kernel<<<dim3(MM / BM, CC / BN, 3), 256, GEMM_SMEM>>>(1, 0, 0, nullptr, nullptr);

    // 5) fused causal attention
    attn_kernel<<<BB * HH, 256, 131072>>>();

    // 6) quantize attention output
    actquant_kernel<<<MM, 256>>>(nullptr, 1);

    // 7) output projection (+bias) straight into d_out
    gemm_kernel<<<dim3(MM / BM, CC / BN, 1), 256, GEMM_SMEM>>>(0, 3, 3, out, bp);
}